// round 5
// baseline (speedup 1.0000x reference)
#include <cuda_runtime.h>
#include <math.h>

#define IN_DIM   256
#define OUT_DIM  256
#define BATCH    4096
#define NROWS    12        // cp k-rows 8..18 (11 rows) + silu row (row 11)

// Scratch (static __device__ — no allocation).
__device__ float g_W [IN_DIM * NROWS * OUT_DIM];   // [i][kk][o], pre-scaled
__device__ float g_Bd[IN_DIM * NROWS * BATCH];     // [i][kk][b]  dense basis (+silu row 11)

// ---------------------------------------------------------------------------
// Kernel 1: W[i][kk][o] = scaling[i][o] * cp[i][o][kk+8]  (kk<11),  row 11 = scaling
// ---------------------------------------------------------------------------
__global__ void prep_w(const float* __restrict__ cp, const float* __restrict__ sc) {
    int i = blockIdx.x;
    int o = threadIdx.x;
    float s = sc[i * OUT_DIM + o];
    const float* cpp = cp + (size_t)(i * OUT_DIM + o) * 19;
    float* wp = g_W + (size_t)i * NROWS * OUT_DIM + o;
#pragma unroll
    for (int kk = 0; kk < 11; kk++)
        wp[kk * OUT_DIM] = s * cpp[kk + 8];
    wp[11 * OUT_DIM] = s;
}

// ---------------------------------------------------------------------------
// Kernel 2: dense 12-wide basis per (i,b), transposed [i][kk][b].
//   x in [0,1): k0l = floor(8x), u = frac(8x); closed-form uniform cubic basis;
//   silu(x) at slot 11, zeros elsewhere.
// ---------------------------------------------------------------------------
__global__ void prep_basis(const float* __restrict__ x) {
    int i = blockIdx.x;
    for (int b = threadIdx.x; b < BATCH; b += blockDim.x) {
        float xv = x[(size_t)b * IN_DIM + i];
        float t8 = xv * 8.0f;
        float fl = floorf(t8);
        float u  = t8 - fl;
        int k0l = min(max((int)fl, 0), 7);
        const float inv6 = 1.0f / 6.0f;
        float u2 = u * u, u3 = u2 * u;
        float omu = 1.0f - u;
        float d[NROWS];
#pragma unroll
        for (int kk = 0; kk < NROWS; kk++) d[kk] = 0.0f;
        d[k0l + 0] = omu * omu * omu * inv6;
        d[k0l + 1] = (3.0f * u3 - 6.0f * u2 + 4.0f) * inv6;
        d[k0l + 2] = (-3.0f * u3 + 3.0f * u2 + 3.0f * u + 1.0f) * inv6;
        d[k0l + 3] = u3 * inv6;
        d[11]      = xv / (1.0f + expf(-xv));       // silu
        float* bp = g_Bd + ((size_t)i * NROWS) * BATCH + b;
#pragma unroll
        for (int kk = 0; kk < NROWS; kk++)
            bp[(size_t)kk * BATCH] = d[kk];
    }
}

// ---------------------------------------------------------------------------
// Packed fp32x2 FMA (FFMA2) on raw 64-bit packs.
// ---------------------------------------------------------------------------
__device__ __forceinline__ void ffma2(unsigned long long& d,
                                      unsigned long long a,
                                      unsigned long long b) {
    asm("fma.rn.f32x2 %0, %1, %2, %0;" : "+l"(d) : "l"(a), "l"(b));
}

union F4U {                 // zero-cost float4 <-> 2x u64 reinterpret
    float4 f;
    struct { unsigned long long lo, hi; } u;
};

// ---------------------------------------------------------------------------
// Kernel 3: branch-free dense contraction, o-paired FFMA2, pre-dup'd B.
// Grid: 256 CTAs = 128 b-tiles(32) x 2 o-tiles(128). 256 threads = 8 warps.
// Warp owns 4 batch rows; lane owns 4 consecutive o (2 o-pairs).
// ---------------------------------------------------------------------------
__device__ __forceinline__ void load_stage(float4* __restrict__ sw,
                                           float4* __restrict__ sb2,
                                           int i, int otile, int btile, int tid) {
    const float4* gw4 = reinterpret_cast<const float4*>(g_W);
    int base = i * (NROWS * 64);                       // float4 units per i
    int j = tid;                                       // W: 384 float4
    sw[j] = gw4[base + (j >> 5) * 64 + otile * 32 + (j & 31)];
    j = tid + 256;
    if (j < NROWS * 32)
        sw[j] = gw4[base + (j >> 5) * 64 + otile * 32 + (j & 31)];
    if (tid < 96) {                                    // B: 12 kk x 32 b (8 quads/kk)
        int kk = tid >> 3;
        int m  = tid & 7;
        float4 v = *reinterpret_cast<const float4*>(
            g_Bd + ((size_t)i * NROWS + kk) * BATCH + btile * 32 + m * 4);
        // duplicate: (b0,b0,b1,b1) and (b2,b2,b3,b3)
        sb2[kk * 16 + m * 2 + 0] = make_float4(v.x, v.x, v.y, v.y);
        sb2[kk * 16 + m * 2 + 1] = make_float4(v.z, v.z, v.w, v.w);
    }
}

__global__ void __launch_bounds__(256) kan_main(float* __restrict__ out) {
    __shared__ float4 s_w [2][NROWS * 32];   // [stage][kk*32 + o_quad]      12 KB
    __shared__ float4 s_b2[2][NROWS * 16];   // [stage][kk*16 + dup-quad]     6 KB

    int tid   = threadIdx.x;
    int warp  = tid >> 5;
    int lane  = tid & 31;
    int otile = blockIdx.x & 1;
    int btile = blockIdx.x >> 1;

    // acc[b][op] : b = 0..3 (warp rows), op = 0..1 (o-pairs), packed f32x2
    unsigned long long acc[4][2];
#pragma unroll
    for (int b = 0; b < 4; b++) { acc[b][0] = 0ull; acc[b][1] = 0ull; }

    load_stage(s_w[0], s_b2[0], 0, otile, btile, tid);
    __syncthreads();

    for (int i = 0; i < IN_DIM; i++) {
        int cur = i & 1;
        if (i + 1 < IN_DIM)
            load_stage(s_w[cur ^ 1], s_b2[cur ^ 1], i + 1, otile, btile, tid);

#pragma unroll
        for (int kk = 0; kk < NROWS; kk++) {
            F4U w;   w.f   = s_w [cur][kk * 32 + lane];          // lane's 4 o
            F4U b01; b01.f = s_b2[cur][kk * 16 + warp * 2 + 0];  // {B0,B0,B1,B1}
            F4U b23; b23.f = s_b2[cur][kk * 16 + warp * 2 + 1];  // {B2,B2,B3,B3}
            ffma2(acc[0][0], b01.u.lo, w.u.lo);
            ffma2(acc[0][1], b01.u.lo, w.u.hi);
            ffma2(acc[1][0], b01.u.hi, w.u.lo);
            ffma2(acc[1][1], b01.u.hi, w.u.hi);
            ffma2(acc[2][0], b23.u.lo, w.u.lo);
            ffma2(acc[2][1], b23.u.lo, w.u.hi);
            ffma2(acc[3][0], b23.u.hi, w.u.lo);
            ffma2(acc[3][1], b23.u.hi, w.u.hi);
        }
        __syncthreads();
    }

    int bb = btile * 32 + warp * 4;
    int oo = otile * 128 + lane * 4;
#pragma unroll
    for (int b = 0; b < 4; b++) {
        F4U r;
        r.u.lo = acc[b][0];
        r.u.hi = acc[b][1];
        *reinterpret_cast<float4*>(out + (size_t)(bb + b) * OUT_DIM + oo) = r.f;
    }
}

// ---------------------------------------------------------------------------
extern "C" void kernel_launch(void* const* d_in, const int* in_sizes, int n_in,
                              void* d_out, int out_size) {
    const float* x  = (const float*)d_in[0];   // [4096, 256]
    const float* cp = (const float*)d_in[1];   // [256, 256, 19]
    const float* sc = (const float*)d_in[2];   // [256, 256]
    float* out = (float*)d_out;                // [4096, 256]

    prep_w    <<<IN_DIM, OUT_DIM>>>(cp, sc);
    prep_basis<<<IN_DIM, 256>>>(x);
    kan_main  <<<256, 256>>>(out);
}

// round 7
// speedup vs baseline: 1.5087x; 1.5087x over previous
#include <cuda_runtime.h>
#include <cuda_bf16.h>
#include <math.h>
#include <stdint.h>

#define IN_DIM   256
#define OUT_DIM  256
#define BATCH    4096
#define NROWS    12
#define KSEG     (IN_DIM * NROWS)      // 3072 dense K per term
#define KA       (2 * KSEG)            // A_cat row: hi | lo           = 6144
#define KB       (3 * KSEG)            // B_cat row: Whi | Wlo | Whi   = 9216
#define KC       64                    // K per chunk
#define NCH      (KB / KC)             // 144
#define CSEG     (KSEG / KC)           // 48

// Scratch (static __device__ — no allocation).
__device__ __nv_bfloat16 g_A[(size_t)BATCH * KA];    // ~50 MB
__device__ __nv_bfloat16 g_B[(size_t)OUT_DIM * KB];  // ~4.7 MB

// ===========================================================================
// Kernel 1: A_cat — dense 12-wide basis/silu per (b,i), split hi|lo bf16.
// ===========================================================================
__global__ void prep_a(const float* __restrict__ x) {
    int b = blockIdx.x;
    int i = threadIdx.x;
    float xv = x[(size_t)b * IN_DIM + i];
    float t8 = xv * 8.0f;
    float fl = floorf(t8);
    float u  = t8 - fl;
    int k0l = min(max((int)fl, 0), 7);
    const float inv6 = 1.0f / 6.0f;
    float u2 = u * u, u3 = u2 * u;
    float omu = 1.0f - u;
    float d[NROWS];
#pragma unroll
    for (int kk = 0; kk < NROWS; kk++) d[kk] = 0.0f;
    d[k0l + 0] = omu * omu * omu * inv6;
    d[k0l + 1] = (3.0f * u3 - 6.0f * u2 + 4.0f) * inv6;
    d[k0l + 2] = (-3.0f * u3 + 3.0f * u2 + 3.0f * u + 1.0f) * inv6;
    d[k0l + 3] = u3 * inv6;
    d[11]      = xv / (1.0f + expf(-xv));       // silu
    __nv_bfloat16* pa = g_A + (size_t)b * KA + i * NROWS;
#pragma unroll
    for (int kk = 0; kk < NROWS; kk++) {
        float v = d[kk];
        __nv_bfloat16 h = __float2bfloat16(v);
        float lo = v - __bfloat162float(h);
        pa[kk]        = h;
        pa[KSEG + kk] = __float2bfloat16(lo);
    }
}

// ===========================================================================
// Kernel 2: B_cat — W[i][kk][o] = sc*cp (row 11 = sc), split Whi|Wlo|Whi.
// ===========================================================================
__global__ void prep_b(const float* __restrict__ cp, const float* __restrict__ sc) {
    int o = blockIdx.x;
    int i = threadIdx.x;
    float s = sc[i * OUT_DIM + o];
    const float* cpp = cp + (size_t)(i * OUT_DIM + o) * 19;
    __nv_bfloat16* pb = g_B + (size_t)o * KB + i * NROWS;
#pragma unroll
    for (int kk = 0; kk < NROWS; kk++) {
        float w = (kk < 11) ? s * cpp[kk + 8] : s;
        __nv_bfloat16 h = __float2bfloat16(w);
        float lo = w - __bfloat162float(h);
        pb[kk]            = h;
        pb[KSEG + kk]     = __float2bfloat16(lo);
        pb[2 * KSEG + kk] = h;
    }
}

// ===========================================================================
// PTX helpers (sm_80-class only: cp.async, ldmatrix, mma.sync — no tcgen05)
// ===========================================================================
__device__ __forceinline__ uint32_t smem_u32(const void* p) {
    uint32_t a;
    asm("{ .reg .u64 t; cvta.to.shared.u64 t, %1; cvt.u32.u64 %0, t; }"
        : "=r"(a) : "l"(p));
    return a;
}
__device__ __forceinline__ void cp16(uint32_t dst, const void* src) {
    asm volatile("cp.async.cg.shared.global [%0], [%1], 16;"
                 :: "r"(dst), "l"(src) : "memory");
}
__device__ __forceinline__ void cp_commit() {
    asm volatile("cp.async.commit_group;" ::: "memory");
}
template <int N>
__device__ __forceinline__ void cp_wait() {
    asm volatile("cp.async.wait_group %0;" :: "n"(N) : "memory");
}
__device__ __forceinline__ void ldm_x4(uint32_t* r, uint32_t addr) {
    asm volatile("ldmatrix.sync.aligned.m8n8.x4.shared.b16 {%0,%1,%2,%3}, [%4];"
                 : "=r"(r[0]), "=r"(r[1]), "=r"(r[2]), "=r"(r[3]) : "r"(addr));
}
__device__ __forceinline__ void mma16816(float* d, const uint32_t* a,
                                         const uint32_t* b) {
    asm volatile(
        "mma.sync.aligned.m16n8k16.row.col.f32.bf16.bf16.f32 "
        "{%0,%1,%2,%3}, {%4,%5,%6,%7}, {%8,%9}, {%0,%1,%2,%3};"
        : "+f"(d[0]), "+f"(d[1]), "+f"(d[2]), "+f"(d[3])
        : "r"(a[0]), "r"(a[1]), "r"(a[2]), "r"(a[3]), "r"(b[0]), "r"(b[1]));
}

// ===========================================================================
// Kernel 3: HMMA GEMM. out[4096,256] = A_cat · B_cat^T.
// CTA: M=128, N=64. grid = 32 btiles x 4 ntiles = 128 CTAs, 256 threads.
// Warps 4(M)x2(N); warp tile 32x32 = 2 mtiles x 4 n8tiles.
// K chunk 64, 2-stage cp.async double buffer.
// Smem rows padded to 144B (72 bf16) — conflict-free ldmatrix.
// ===========================================================================
#define ROWB  144                       // bytes per padded smem row
#define ASTG  (128 * ROWB)              // 18432
#define BSTG  (64 * ROWB)               // 9216
#define SMTOT (2 * ASTG + 2 * BSTG)     // 55296

__global__ void __launch_bounds__(256) kan_mma(float* __restrict__ out) {
    extern __shared__ char smem[];
    uint32_t sbase = smem_u32(smem);
    uint32_t sA[2] = { sbase,              sbase + ASTG };
    uint32_t sB[2] = { sbase + 2 * ASTG,   sbase + 2 * ASTG + BSTG };

    int tid  = threadIdx.x;
    int wid  = tid >> 5;
    int lane = tid & 31;
    int btile = blockIdx.x >> 2;          // 0..31
    int ntile = blockIdx.x & 3;           // 0..3
    int warp_m = wid >> 1;                // 0..3
    int warp_n = wid & 1;                 // 0..1

    // ---- cp.async per-thread mapping (A: 4 ops, B: 2 ops per chunk) ----
    int u      = tid & 7;                 // 16B unit in row
    int row0   = tid >> 3;                // 0..31
    const __nv_bfloat16* gA[4];
    uint32_t dA[4];
#pragma unroll
    for (int j = 0; j < 4; j++) {
        int r = row0 + 32 * j;
        gA[j] = g_A + (size_t)(btile * 128 + r) * KA + u * 8;
        dA[j] = r * ROWB + u * 16;
    }
    const __nv_bfloat16* gB[2];
    uint32_t dB[2];
#pragma unroll
    for (int j = 0; j < 2; j++) {
        int r = row0 + 32 * j;
        gB[j] = g_B + (size_t)(ntile * 64 + r) * KB + u * 8;
        dB[j] = r * ROWB + u * 16;
    }

    // ---- ldmatrix per-lane base offsets ----
    // A x4: row = mbase + (lane&7) + 8*((lane>>3)&1), k half = (lane>>4)
    uint32_t a_off[2];
#pragma unroll
    for (int mt = 0; mt < 2; mt++) {
        int r = warp_m * 32 + mt * 16 + (lane & 7) + 8 * ((lane >> 3) & 1);
        a_off[mt] = r * ROWB + (lane >> 4) * 16;
    }
    // B x4 (2 n8-tiles per load): row = nbase + pair*16 + 8*((lane>>4)&1) + (lane&7),
    // k half = (lane>>3)&1
    uint32_t b_off[2];
#pragma unroll
    for (int np = 0; np < 2; np++) {
        int r = warp_n * 32 + np * 16 + ((lane >> 4) & 1) * 8 + (lane & 7);
        b_off[np] = r * ROWB + ((lane >> 3) & 1) * 16;
    }

    float acc[2][4][4];
#pragma unroll
    for (int mt = 0; mt < 2; mt++)
#pragma unroll
        for (int nt = 0; nt < 4; nt++)
#pragma unroll
            for (int q = 0; q < 4; q++) acc[mt][nt][q] = 0.0f;

    // ---- issue helper (macro to keep everything in-regs) ----
#define ISSUE(c, s) do {                                                        \
        int _c = (c);                                                           \
        int _seg = _c / CSEG;                                                   \
        int _aoff = ((_seg == 2) ? KSEG : 0) + (_c - _seg * CSEG) * KC;         \
        int _boff = _c * KC;                                                    \
        _Pragma("unroll")                                                       \
        for (int j = 0; j < 4; j++)                                             \
            cp16(sA[s] + dA[j], gA[j] + _aoff);                                 \
        _Pragma("unroll")                                                       \
        for (int j = 0; j < 2; j++)                                             \
            cp16(sB[s] + dB[j], gB[j] + _boff);                                 \
        cp_commit();                                                            \
    } while (0)

    ISSUE(0, 0);
    ISSUE(1, 1);

    for (int c = 0; c < NCH; c++) {
        int s = c & 1;
        if (c + 2 < NCH) cp_wait<1>(); else cp_wait<0>();
        __syncthreads();

#pragma unroll
        for (int ks = 0; ks < 4; ks++) {
            uint32_t kb = ks * 32;                 // 16 bf16 = 32B per kstep
            uint32_t afr[2][4], bfr[2][4];
#pragma unroll
            for (int mt = 0; mt < 2; mt++)
                ldm_x4(afr[mt], sA[s] + a_off[mt] + kb);
#pragma unroll
            for (int np = 0; np < 2; np++)
                ldm_x4(bfr[np], sB[s] + b_off[np] + kb);
#pragma unroll
            for (int mt = 0; mt < 2; mt++) {
#pragma unroll
                for (int nt = 0; nt < 4; nt++) {
                    uint32_t bb[2] = { bfr[nt >> 1][(nt & 1) * 2 + 0],
                                       bfr[nt >> 1][(nt & 1) * 2 + 1] };
                    mma16816(acc[mt][nt], afr[mt], bb);
                }
            }
        }

        __syncthreads();
        if (c + 2 < NCH) ISSUE(c + 2, s);
    }

    // ---- epilogue ----
    int mg = btile * 128 + warp_m * 32 + (lane >> 2);
    int ng = ntile * 64 + warp_n * 32 + (lane & 3) * 2;
#pragma unroll
    for (int mt = 0; mt < 2; mt++) {
#pragma unroll
        for (int nt = 0; nt < 4; nt++) {
            int m0 = mg + mt * 16;
            int n0 = ng + nt * 8;
            float2 v0 = make_float2(acc[mt][nt][0], acc[mt][nt][1]);
            float2 v1 = make_float2(acc[mt][nt][2], acc[mt][nt][3]);
            *reinterpret_cast<float2*>(out + (size_t)m0 * OUT_DIM + n0) = v0;
            *reinterpret_cast<float2*>(out + (size_t)(m0 + 8) * OUT_DIM + n0) = v1;
        }
    }
#undef ISSUE
}

// ---------------------------------------------------------------------------
extern "C" void kernel_launch(void* const* d_in, const int* in_sizes, int n_in,
                              void* d_out, int out_size) {
    const float* x  = (const float*)d_in[0];   // [4096, 256]
    const float* cp = (const float*)d_in[1];   // [256, 256, 19]
    const float* sc = (const float*)d_in[2];   // [256, 256]
    float* out = (float*)d_out;                // [4096, 256]

    cudaFuncSetAttribute(kan_mma, cudaFuncAttributeMaxDynamicSharedMemorySize,
                         SMTOT);

    prep_a<<<BATCH,   IN_DIM>>>(x);
    prep_b<<<OUT_DIM, IN_DIM>>>(cp, sc);
    kan_mma<<<128, 256, SMTOT>>>(out);
}

// round 8
// speedup vs baseline: 2.3914x; 1.5851x over previous
#include <cuda_runtime.h>
#include <cuda_bf16.h>
#include <math.h>
#include <stdint.h>

#define IN_DIM   256
#define OUT_DIM  256
#define BATCH    4096
#define NROWS    12
#define KSEG     (IN_DIM * NROWS)      // 3072 dense K per term
#define KA       (2 * KSEG)            // A_cat row: hi | lo           = 6144
#define KB       (3 * KSEG)            // B_cat row: Whi | Wlo | Whi   = 9216
#define KC       64                    // K per chunk
#define NCH      (KB / KC)             // 144
#define CSEG     (KSEG / KC)           // 48

// Scratch (static __device__ — no allocation).
__device__ __nv_bfloat16 g_A[(size_t)BATCH * KA];    // ~50 MB
__device__ __nv_bfloat16 g_B[(size_t)OUT_DIM * KB];  // ~4.7 MB

// ===========================================================================
// Kernel 1: A_cat — dense 12-wide basis/silu per (b,i), split hi|lo bf16.
// Smem-staged: pack 12+12 bf16 into u32 pairs, then coalesced uint4 stores.
// ===========================================================================
__global__ void __launch_bounds__(256) prep_a(const float* __restrict__ x) {
    __shared__ uint32_t st[3072];                 // 12 KB row image for batch b
    int b = blockIdx.x;
    int i = threadIdx.x;
    float xv = x[(size_t)b * IN_DIM + i];
    float t8 = xv * 8.0f;
    float fl = floorf(t8);
    float u  = t8 - fl;
    int k0l = min(max((int)fl, 0), 7);
    const float inv6 = 1.0f / 6.0f;
    float u2 = u * u, u3 = u2 * u;
    float omu = 1.0f - u;
    float d[NROWS];
#pragma unroll
    for (int kk = 0; kk < NROWS; kk++) d[kk] = 0.0f;
    d[k0l + 0] = omu * omu * omu * inv6;
    d[k0l + 1] = (3.0f * u3 - 6.0f * u2 + 4.0f) * inv6;
    d[k0l + 2] = (-3.0f * u3 + 3.0f * u2 + 3.0f * u + 1.0f) * inv6;
    d[k0l + 3] = u3 * inv6;
    d[11]      = xv / (1.0f + expf(-xv));         // silu

    unsigned short hb[NROWS], lb[NROWS];
#pragma unroll
    for (int kk = 0; kk < NROWS; kk++) {
        float v = d[kk];
        __nv_bfloat16 h = __float2bfloat16(v);
        float lo = v - __bfloat162float(h);
        __nv_bfloat16 l = __float2bfloat16(lo);
        hb[kk] = *reinterpret_cast<unsigned short*>(&h);
        lb[kk] = *reinterpret_cast<unsigned short*>(&l);
    }
#pragma unroll
    for (int j = 0; j < 6; j++) {
        st[i * 6 + j]        = (uint32_t)hb[2 * j] | ((uint32_t)hb[2 * j + 1] << 16);
        st[1536 + i * 6 + j] = (uint32_t)lb[2 * j] | ((uint32_t)lb[2 * j + 1] << 16);
    }
    __syncthreads();

    const uint4* s4 = reinterpret_cast<const uint4*>(st);
    uint4* g4 = reinterpret_cast<uint4*>(g_A) + (size_t)b * 768;
#pragma unroll
    for (int p = 0; p < 3; p++)
        g4[p * 256 + i] = s4[p * 256 + i];
}

// ===========================================================================
// Kernel 2: B_cat — W[i][kk][o] = sc*cp (row 11 = sc), split Whi|Wlo|Whi.
// ===========================================================================
__global__ void prep_b(const float* __restrict__ cp, const float* __restrict__ sc) {
    int o = blockIdx.x;
    int i = threadIdx.x;
    float s = sc[i * OUT_DIM + o];
    const float* cpp = cp + (size_t)(i * OUT_DIM + o) * 19;
    __nv_bfloat16* pb = g_B + (size_t)o * KB + i * NROWS;
#pragma unroll
    for (int kk = 0; kk < NROWS; kk++) {
        float w = (kk < 11) ? s * cpp[kk + 8] : s;
        __nv_bfloat16 h = __float2bfloat16(w);
        float lo = w - __bfloat162float(h);
        pb[kk]            = h;
        pb[KSEG + kk]     = __float2bfloat16(lo);
        pb[2 * KSEG + kk] = h;
    }
}

// ===========================================================================
// PTX helpers (sm_80-class only: cp.async, ldmatrix, mma.sync — no tcgen05)
// ===========================================================================
__device__ __forceinline__ uint32_t smem_u32(const void* p) {
    uint32_t a;
    asm("{ .reg .u64 t; cvta.to.shared.u64 t, %1; cvt.u32.u64 %0, t; }"
        : "=r"(a) : "l"(p));
    return a;
}
__device__ __forceinline__ void cp16(uint32_t dst, const void* src) {
    asm volatile("cp.async.cg.shared.global [%0], [%1], 16;"
                 :: "r"(dst), "l"(src) : "memory");
}
__device__ __forceinline__ void cp_commit() {
    asm volatile("cp.async.commit_group;" ::: "memory");
}
template <int N>
__device__ __forceinline__ void cp_wait() {
    asm volatile("cp.async.wait_group %0;" :: "n"(N) : "memory");
}
__device__ __forceinline__ void ldm_x4(uint32_t* r, uint32_t addr) {
    asm volatile("ldmatrix.sync.aligned.m8n8.x4.shared.b16 {%0,%1,%2,%3}, [%4];"
                 : "=r"(r[0]), "=r"(r[1]), "=r"(r[2]), "=r"(r[3]) : "r"(addr));
}
__device__ __forceinline__ void mma16816(float* d, const uint32_t* a,
                                         const uint32_t* b) {
    asm volatile(
        "mma.sync.aligned.m16n8k16.row.col.f32.bf16.bf16.f32 "
        "{%0,%1,%2,%3}, {%4,%5,%6,%7}, {%8,%9}, {%0,%1,%2,%3};"
        : "+f"(d[0]), "+f"(d[1]), "+f"(d[2]), "+f"(d[3])
        : "r"(a[0]), "r"(a[1]), "r"(a[2]), "r"(a[3]), "r"(b[0]), "r"(b[1]));
}

// ===========================================================================
// Kernel 3: HMMA GEMM. out[4096,256] = A_cat · B_cat^T.
// CTA: M=128, N=64. grid = 32 btiles x 4 ntiles = 128 CTAs, 256 threads.
// Warps 4(M)x2(N); warp tile 32x32.
// 3-stage cp.async pipeline, single __syncthreads per chunk:
//   iter c: wait_group<1> (chunk c landed) -> sync -> issue chunk c+2 into
//   stage (c+2)%3 (freed at iter c-1, safe past this sync) -> compute chunk c.
// Smem rows padded to 144B (stride 36 words ≡ 4 mod 32 -> conflict-free ldmatrix).
// ===========================================================================
#define ROWB  144                       // bytes per padded smem row
#define ASTG  (128 * ROWB)              // 18432
#define BSTG  (64 * ROWB)               // 9216
#define STG_B (ASTG + BSTG)             // 27648 per stage
#define SMTOT (3 * STG_B)               // 82944

__global__ void __launch_bounds__(256) kan_mma(float* __restrict__ out) {
    extern __shared__ char smem[];
    uint32_t sbase = smem_u32(smem);
    uint32_t sA[3], sB[3];
#pragma unroll
    for (int s = 0; s < 3; s++) {
        sA[s] = sbase + s * STG_B;
        sB[s] = sbase + s * STG_B + ASTG;
    }

    int tid  = threadIdx.x;
    int wid  = tid >> 5;
    int lane = tid & 31;
    int btile = blockIdx.x >> 2;          // 0..31
    int ntile = blockIdx.x & 3;           // 0..3
    int warp_m = wid >> 1;                // 0..3
    int warp_n = wid & 1;                 // 0..1

    // ---- cp.async per-thread mapping (A: 4 ops, B: 2 ops per chunk) ----
    int u      = tid & 7;                 // 16B unit in row
    int row0   = tid >> 3;                // 0..31
    const __nv_bfloat16* gA[4];
    uint32_t dA[4];
#pragma unroll
    for (int j = 0; j < 4; j++) {
        int r = row0 + 32 * j;
        gA[j] = g_A + (size_t)(btile * 128 + r) * KA + u * 8;
        dA[j] = r * ROWB + u * 16;
    }
    const __nv_bfloat16* gB[2];
    uint32_t dB[2];
#pragma unroll
    for (int j = 0; j < 2; j++) {
        int r = row0 + 32 * j;
        gB[j] = g_B + (size_t)(ntile * 64 + r) * KB + u * 8;
        dB[j] = r * ROWB + u * 16;
    }

    // ---- ldmatrix per-lane base offsets ----
    uint32_t a_off[2];
#pragma unroll
    for (int mt = 0; mt < 2; mt++) {
        int r = warp_m * 32 + mt * 16 + (lane & 7) + 8 * ((lane >> 3) & 1);
        a_off[mt] = r * ROWB + (lane >> 4) * 16;
    }
    uint32_t b_off[2];
#pragma unroll
    for (int np = 0; np < 2; np++) {
        int r = warp_n * 32 + np * 16 + ((lane >> 4) & 1) * 8 + (lane & 7);
        b_off[np] = r * ROWB + ((lane >> 3) & 1) * 16;
    }

    float acc[2][4][4];
#pragma unroll
    for (int mt = 0; mt < 2; mt++)
#pragma unroll
        for (int nt = 0; nt < 4; nt++)
#pragma unroll
            for (int q = 0; q < 4; q++) acc[mt][nt][q] = 0.0f;

#define ISSUE(c, s) do {                                                        \
        int _c = (c);                                                           \
        int _seg = _c / CSEG;                                                   \
        int _aoff = ((_seg == 2) ? KSEG : 0) + (_c - _seg * CSEG) * KC;         \
        int _boff = _c * KC;                                                    \
        _Pragma("unroll")                                                       \
        for (int j = 0; j < 4; j++)                                             \
            cp16(sA[s] + dA[j], gA[j] + _aoff);                                 \
        _Pragma("unroll")                                                       \
        for (int j = 0; j < 2; j++)                                             \
            cp16(sB[s] + dB[j], gB[j] + _boff);                                 \
        cp_commit();                                                            \
    } while (0)

    // prologue: 2 chunks in flight
    ISSUE(0, 0);
    ISSUE(1, 1);

    for (int c = 0; c < NCH; c++) {
        int s = c % 3;
        if (c + 1 < NCH) cp_wait<1>(); else cp_wait<0>();
        __syncthreads();

        if (c + 2 < NCH) ISSUE(c + 2, (c + 2) % 3);   // into stage freed at c-1

#pragma unroll
        for (int ks = 0; ks < 4; ks++) {
            uint32_t kb = ks * 32;
            uint32_t afr[2][4], bfr[2][4];
#pragma unroll
            for (int mt = 0; mt < 2; mt++)
                ldm_x4(afr[mt], sA[s] + a_off[mt] + kb);
#pragma unroll
            for (int np = 0; np < 2; np++)
                ldm_x4(bfr[np], sB[s] + b_off[np] + kb);
#pragma unroll
            for (int mt = 0; mt < 2; mt++) {
#pragma unroll
                for (int nt = 0; nt < 4; nt++) {
                    uint32_t bb[2] = { bfr[nt >> 1][(nt & 1) * 2 + 0],
                                       bfr[nt >> 1][(nt & 1) * 2 + 1] };
                    mma16816(acc[mt][nt], afr[mt], bb);
                }
            }
        }
    }

    // ---- epilogue ----
    int mg = btile * 128 + warp_m * 32 + (lane >> 2);
    int ng = ntile * 64 + warp_n * 32 + (lane & 3) * 2;
#pragma unroll
    for (int mt = 0; mt < 2; mt++) {
#pragma unroll
        for (int nt = 0; nt < 4; nt++) {
            int m0 = mg + mt * 16;
            int n0 = ng + nt * 8;
            float2 v0 = make_float2(acc[mt][nt][0], acc[mt][nt][1]);
            float2 v1 = make_float2(acc[mt][nt][2], acc[mt][nt][3]);
            *reinterpret_cast<float2*>(out + (size_t)m0 * OUT_DIM + n0) = v0;
            *reinterpret_cast<float2*>(out + (size_t)(m0 + 8) * OUT_DIM + n0) = v1;
        }
    }
#undef ISSUE
}

// ---------------------------------------------------------------------------
extern "C" void kernel_launch(void* const* d_in, const int* in_sizes, int n_in,
                              void* d_out, int out_size) {
    const float* x  = (const float*)d_in[0];   // [4096, 256]
    const float* cp = (const float*)d_in[1];   // [256, 256, 19]
    const float* sc = (const float*)d_in[2];   // [256, 256]
    float* out = (float*)d_out;                // [4096, 256]

    cudaFuncSetAttribute(kan_mma, cudaFuncAttributeMaxDynamicSharedMemorySize,
                         SMTOT);

    prep_a<<<BATCH,   IN_DIM>>>(x);
    prep_b<<<OUT_DIM, IN_DIM>>>(cp, sc);
    kan_mma<<<128, 256, SMTOT>>>(out);
}

// round 9
// speedup vs baseline: 2.6698x; 1.1164x over previous
#include <cuda_runtime.h>
#include <cuda_bf16.h>
#include <math.h>
#include <stdint.h>

#define IN_DIM   256
#define OUT_DIM  256
#define BATCH    4096
#define NROWS    12
#define KSEG     (IN_DIM * NROWS)      // 3072 dense K per term
#define KA       (2 * KSEG)            // A_cat row: hi | lo           = 6144
#define KB       (3 * KSEG)            // B_cat row: Whi | Wlo | Whi   = 9216
#define KC       128                   // K per chunk
#define NCH      (KB / KC)             // 72
#define CSEG     (KSEG / KC)           // 24

// Scratch (static __device__ — no allocation).
__device__ __nv_bfloat16 g_A[(size_t)BATCH * KA];    // ~50 MB (L2-resident)
__device__ __nv_bfloat16 g_B[(size_t)OUT_DIM * KB];  // ~4.7 MB

// ===========================================================================
// Kernel 1: A_cat — dense 12-wide basis/silu per (b,i), split hi|lo bf16.
// Smem-staged: pack 12+12 bf16 into u32 pairs, then coalesced uint4 stores.
// ===========================================================================
__global__ void __launch_bounds__(256) prep_a(const float* __restrict__ x) {
    __shared__ uint32_t st[3072];                 // 12 KB row image for batch b
    int b = blockIdx.x;
    int i = threadIdx.x;
    float xv = x[(size_t)b * IN_DIM + i];
    float t8 = xv * 8.0f;
    float fl = floorf(t8);
    float u  = t8 - fl;
    int k0l = min(max((int)fl, 0), 7);
    const float inv6 = 1.0f / 6.0f;
    float u2 = u * u, u3 = u2 * u;
    float omu = 1.0f - u;
    float d[NROWS];
#pragma unroll
    for (int kk = 0; kk < NROWS; kk++) d[kk] = 0.0f;
    d[k0l + 0] = omu * omu * omu * inv6;
    d[k0l + 1] = (3.0f * u3 - 6.0f * u2 + 4.0f) * inv6;
    d[k0l + 2] = (-3.0f * u3 + 3.0f * u2 + 3.0f * u + 1.0f) * inv6;
    d[k0l + 3] = u3 * inv6;
    d[11]      = xv / (1.0f + expf(-xv));         // silu

    unsigned short hb[NROWS], lb[NROWS];
#pragma unroll
    for (int kk = 0; kk < NROWS; kk++) {
        float v = d[kk];
        __nv_bfloat16 h = __float2bfloat16(v);
        float lo = v - __bfloat162float(h);
        __nv_bfloat16 l = __float2bfloat16(lo);
        hb[kk] = *reinterpret_cast<unsigned short*>(&h);
        lb[kk] = *reinterpret_cast<unsigned short*>(&l);
    }
#pragma unroll
    for (int j = 0; j < 6; j++) {
        st[i * 6 + j]        = (uint32_t)hb[2 * j] | ((uint32_t)hb[2 * j + 1] << 16);
        st[1536 + i * 6 + j] = (uint32_t)lb[2 * j] | ((uint32_t)lb[2 * j + 1] << 16);
    }
    __syncthreads();

    const uint4* s4 = reinterpret_cast<const uint4*>(st);
    uint4* g4 = reinterpret_cast<uint4*>(g_A) + (size_t)b * 768;
#pragma unroll
    for (int p = 0; p < 3; p++)
        g4[p * 256 + i] = s4[p * 256 + i];
}

// ===========================================================================
// Kernel 2: B_cat — W[i][kk][o] = sc*cp (row 11 = sc), split Whi|Wlo|Whi.
// ===========================================================================
__global__ void prep_b(const float* __restrict__ cp, const float* __restrict__ sc) {
    int o = blockIdx.x;
    int i = threadIdx.x;
    float s = sc[i * OUT_DIM + o];
    const float* cpp = cp + (size_t)(i * OUT_DIM + o) * 19;
    __nv_bfloat16* pb = g_B + (size_t)o * KB + i * NROWS;
#pragma unroll
    for (int kk = 0; kk < NROWS; kk++) {
        float w = (kk < 11) ? s * cpp[kk + 8] : s;
        __nv_bfloat16 h = __float2bfloat16(w);
        float lo = w - __bfloat162float(h);
        pb[kk]            = h;
        pb[KSEG + kk]     = __float2bfloat16(lo);
        pb[2 * KSEG + kk] = h;
    }
}

// ===========================================================================
// PTX helpers (sm_80-class only: cp.async, ldmatrix, mma.sync — no tcgen05)
// ===========================================================================
__device__ __forceinline__ uint32_t smem_u32(const void* p) {
    uint32_t a;
    asm("{ .reg .u64 t; cvta.to.shared.u64 t, %1; cvt.u32.u64 %0, t; }"
        : "=r"(a) : "l"(p));
    return a;
}
__device__ __forceinline__ void cp16(uint32_t dst, const void* src) {
    asm volatile("cp.async.cg.shared.global [%0], [%1], 16;"
                 :: "r"(dst), "l"(src) : "memory");
}
__device__ __forceinline__ void cp_commit() {
    asm volatile("cp.async.commit_group;" ::: "memory");
}
template <int N>
__device__ __forceinline__ void cp_wait() {
    asm volatile("cp.async.wait_group %0;" :: "n"(N) : "memory");
}
__device__ __forceinline__ void ldm_x4(uint32_t* r, uint32_t addr) {
    asm volatile("ldmatrix.sync.aligned.m8n8.x4.shared.b16 {%0,%1,%2,%3}, [%4];"
                 : "=r"(r[0]), "=r"(r[1]), "=r"(r[2]), "=r"(r[3]) : "r"(addr));
}
__device__ __forceinline__ void mma16816(float* d, const uint32_t* a,
                                         const uint32_t* b) {
    asm volatile(
        "mma.sync.aligned.m16n8k16.row.col.f32.bf16.bf16.f32 "
        "{%0,%1,%2,%3}, {%4,%5,%6,%7}, {%8,%9}, {%0,%1,%2,%3};"
        : "+f"(d[0]), "+f"(d[1]), "+f"(d[2]), "+f"(d[3])
        : "r"(a[0]), "r"(a[1]), "r"(a[2]), "r"(a[3]), "r"(b[0]), "r"(b[1]));
}

// ===========================================================================
// Kernel 3: HMMA GEMM. out[4096,256] = A_cat · B_cat^T.
// CTA: M=128, N=64. grid = 32 btiles x 4 ntiles = 128 CTAs, 256 threads.
// Warps 4(M)x2(N); warp tile 32x32.
// KC=128 (8 k-steps per barrier), 3-stage cp.async pipeline, ONE sync/chunk.
// Smem rows 272B stride (r*272 mod 128 = r*16 -> conflict-free ldmatrix).
// ===========================================================================
#define ROWB  272                       // bytes per padded smem row (256 data)
#define ASTG  (128 * ROWB)              // 34816
#define BSTG  (64 * ROWB)               // 17408
#define STG_B (ASTG + BSTG)             // 52224 per stage
#define SMTOT (3 * STG_B)               // 156672

__global__ void __launch_bounds__(256) kan_mma(float* __restrict__ out) {
    extern __shared__ char smem[];
    uint32_t sbase = smem_u32(smem);
    uint32_t sA[3], sB[3];
#pragma unroll
    for (int s = 0; s < 3; s++) {
        sA[s] = sbase + s * STG_B;
        sB[s] = sbase + s * STG_B + ASTG;
    }

    int tid  = threadIdx.x;
    int wid  = tid >> 5;
    int lane = tid & 31;
    int btile = blockIdx.x >> 2;          // 0..31
    int ntile = blockIdx.x & 3;           // 0..3
    int warp_m = wid >> 1;                // 0..3
    int warp_n = wid & 1;                 // 0..1

    // ---- cp.async per-thread mapping (A: 8 ops, B: 4 ops per chunk) ----
    int u      = tid & 15;                // 16B unit in 256B row
    int row0   = tid >> 4;                // 0..15
    const __nv_bfloat16* gA[8];
    uint32_t dA[8];
#pragma unroll
    for (int j = 0; j < 8; j++) {
        int r = row0 + 16 * j;
        gA[j] = g_A + (size_t)(btile * 128 + r) * KA + u * 8;
        dA[j] = r * ROWB + u * 16;
    }
    const __nv_bfloat16* gB[4];
    uint32_t dB[4];
#pragma unroll
    for (int j = 0; j < 4; j++) {
        int r = row0 + 16 * j;
        gB[j] = g_B + (size_t)(ntile * 64 + r) * KB + u * 8;
        dB[j] = r * ROWB + u * 16;
    }

    // ---- ldmatrix per-lane base offsets ----
    uint32_t a_off[2];
#pragma unroll
    for (int mt = 0; mt < 2; mt++) {
        int r = warp_m * 32 + mt * 16 + (lane & 7) + 8 * ((lane >> 3) & 1);
        a_off[mt] = r * ROWB + (lane >> 4) * 16;
    }
    uint32_t b_off[2];
#pragma unroll
    for (int np = 0; np < 2; np++) {
        int r = warp_n * 32 + np * 16 + ((lane >> 4) & 1) * 8 + (lane & 7);
        b_off[np] = r * ROWB + ((lane >> 3) & 1) * 16;
    }

    float acc[2][4][4];
#pragma unroll
    for (int mt = 0; mt < 2; mt++)
#pragma unroll
        for (int nt = 0; nt < 4; nt++)
#pragma unroll
            for (int q = 0; q < 4; q++) acc[mt][nt][q] = 0.0f;

#define ISSUE(c, s) do {                                                        \
        int _c = (c);                                                           \
        int _seg = _c / CSEG;                                                   \
        int _aoff = ((_seg == 2) ? KSEG : 0) + (_c - _seg * CSEG) * KC;         \
        int _boff = _c * KC;                                                    \
        _Pragma("unroll")                                                       \
        for (int j = 0; j < 8; j++)                                             \
            cp16(sA[s] + dA[j], gA[j] + _aoff);                                 \
        _Pragma("unroll")                                                       \
        for (int j = 0; j < 4; j++)                                             \
            cp16(sB[s] + dB[j], gB[j] + _boff);                                 \
        cp_commit();                                                            \
    } while (0)

    // prologue: 2 chunks in flight
    ISSUE(0, 0);
    ISSUE(1, 1);

    for (int c = 0; c < NCH; c++) {
        int s = c % 3;
        if (c + 1 < NCH) cp_wait<1>(); else cp_wait<0>();
        __syncthreads();

        if (c + 2 < NCH) ISSUE(c + 2, (c + 2) % 3);   // stage freed at iter c-1

#pragma unroll
        for (int ks = 0; ks < 8; ks++) {
            uint32_t kb = ks * 32;
            uint32_t afr[2][4], bfr[2][4];
#pragma unroll
            for (int mt = 0; mt < 2; mt++)
                ldm_x4(afr[mt], sA[s] + a_off[mt] + kb);
#pragma unroll
            for (int np = 0; np < 2; np++)
                ldm_x4(bfr[np], sB[s] + b_off[np] + kb);
#pragma unroll
            for (int mt = 0; mt < 2; mt++) {
#pragma unroll
                for (int nt = 0; nt < 4; nt++) {
                    uint32_t bb[2] = { bfr[nt >> 1][(nt & 1) * 2 + 0],
                                       bfr[nt >> 1][(nt & 1) * 2 + 1] };
                    mma16816(acc[mt][nt], afr[mt], bb);
                }
            }
        }
    }

    // ---- epilogue ----
    int mg = btile * 128 + warp_m * 32 + (lane >> 2);
    int ng = ntile * 64 + warp_n * 32 + (lane & 3) * 2;
#pragma unroll
    for (int mt = 0; mt < 2; mt++) {
#pragma unroll
        for (int nt = 0; nt < 4; nt++) {
            int m0 = mg + mt * 16;
            int n0 = ng + nt * 8;
            float2 v0 = make_float2(acc[mt][nt][0], acc[mt][nt][1]);
            float2 v1 = make_float2(acc[mt][nt][2], acc[mt][nt][3]);
            *reinterpret_cast<float2*>(out + (size_t)m0 * OUT_DIM + n0) = v0;
            *reinterpret_cast<float2*>(out + (size_t)(m0 + 8) * OUT_DIM + n0) = v1;
        }
    }
#undef ISSUE
}

// ---------------------------------------------------------------------------
extern "C" void kernel_launch(void* const* d_in, const int* in_sizes, int n_in,
                              void* d_out, int out_size) {
    const float* x  = (const float*)d_in[0];   // [4096, 256]
    const float* cp = (const float*)d_in[1];   // [256, 256, 19]
    const float* sc = (const float*)d_in[2];   // [256, 256]
    float* out = (float*)d_out;                // [4096, 256]

    cudaFuncSetAttribute(kan_mma, cudaFuncAttributeMaxDynamicSharedMemorySize,
                         SMTOT);

    prep_a<<<BATCH,   IN_DIM>>>(x);
    prep_b<<<OUT_DIM, IN_DIM>>>(cp, sc);
    kan_mma<<<128, 256, SMTOT>>>(out);
}